// round 1
// baseline (speedup 1.0000x reference)
#include <cuda_runtime.h>
#include <cstdint>
#include <cstddef>

// Which JAX threefry scheme to emulate. Modern JAX (>=0.4.36) defaults to
// jax_threefry_partitionable=True. If rel_err shows wholesale seq mismatch,
// flip this to 0 (legacy "original" counter layout).
#define JAX_PARTITIONABLE 1

static constexpr int B_   = 512;
static constexpr int H_   = 512;
static constexpr int E_   = 512;
static constexpr int V_   = 2048;
static constexpr int L_   = 32;
static constexpr int LP1  = 33;
static constexpr int IND  = 1024;

// ---------------- persistent scratch (device globals; no allocation) ---------
__device__ float g_h[B_ * H_];
__device__ float g_c[B_ * H_];
__device__ float g_e[B_ * E_];
__device__ float g_gates[B_ * 4 * H_];
__device__ float g_logits[B_ * V_];

// ---------------- threefry2x32 (20 rounds), host+device ---------------------
__host__ __device__ __forceinline__ uint32_t rotl32(uint32_t x, int d) {
    return (x << d) | (x >> (32 - d));
}

__host__ __device__ inline void tf2x32(uint32_t k0, uint32_t k1,
                                       uint32_t x0, uint32_t x1,
                                       uint32_t* o0, uint32_t* o1) {
    const uint32_t ks0 = k0, ks1 = k1, ks2 = k0 ^ k1 ^ 0x1BD11BDAu;
    x0 += ks0; x1 += ks1;
    // group 1 (rot set A: 13,15,26,6)
    x0 += x1; x1 = rotl32(x1, 13); x1 ^= x0;
    x0 += x1; x1 = rotl32(x1, 15); x1 ^= x0;
    x0 += x1; x1 = rotl32(x1, 26); x1 ^= x0;
    x0 += x1; x1 = rotl32(x1, 6);  x1 ^= x0;
    x0 += ks1; x1 += ks2 + 1u;
    // group 2 (rot set B: 17,29,16,24)
    x0 += x1; x1 = rotl32(x1, 17); x1 ^= x0;
    x0 += x1; x1 = rotl32(x1, 29); x1 ^= x0;
    x0 += x1; x1 = rotl32(x1, 16); x1 ^= x0;
    x0 += x1; x1 = rotl32(x1, 24); x1 ^= x0;
    x0 += ks2; x1 += ks0 + 2u;
    // group 3 (A)
    x0 += x1; x1 = rotl32(x1, 13); x1 ^= x0;
    x0 += x1; x1 = rotl32(x1, 15); x1 ^= x0;
    x0 += x1; x1 = rotl32(x1, 26); x1 ^= x0;
    x0 += x1; x1 = rotl32(x1, 6);  x1 ^= x0;
    x0 += ks0; x1 += ks1 + 3u;
    // group 4 (B)
    x0 += x1; x1 = rotl32(x1, 17); x1 ^= x0;
    x0 += x1; x1 = rotl32(x1, 29); x1 ^= x0;
    x0 += x1; x1 = rotl32(x1, 16); x1 ^= x0;
    x0 += x1; x1 = rotl32(x1, 24); x1 ^= x0;
    x0 += ks1; x1 += ks2 + 4u;
    // group 5 (A)
    x0 += x1; x1 = rotl32(x1, 13); x1 ^= x0;
    x0 += x1; x1 = rotl32(x1, 15); x1 ^= x0;
    x0 += x1; x1 = rotl32(x1, 26); x1 ^= x0;
    x0 += x1; x1 = rotl32(x1, 6);  x1 ^= x0;
    x0 += ks2; x1 += ks0 + 5u;
    *o0 = x0; *o1 = x1;
}

// ---------------- GEMM: C[M,N] = A0@W0 (+ A1@W1) + bias0 (+ bias1) ----------
// A row-major [M,K], W row-major [K,N]. M,N multiples of 64; K multiple of 16.
__global__ __launch_bounds__(256) void gemm_kernel(
    const float* __restrict__ A0, const float* __restrict__ W0, int K0,
    const float* __restrict__ A1, const float* __restrict__ W1, int K1,
    const float* __restrict__ bias0, const float* __restrict__ bias1,
    float* __restrict__ C, int N)
{
    __shared__ __align__(16) float As[16][68];
    __shared__ __align__(16) float Bs[16][64];
    const int tid = threadIdx.x;
    const int bn = blockIdx.x * 64, bm = blockIdx.y * 64;
    const int tx = tid & 15, ty = tid >> 4;

    float acc[4][4] = {};

    const float* Aarr[2] = {A0, A1};
    const float* Warr[2] = {W0, W1};
    const int    Karr[2] = {K0, K1};

    const int ar = tid >> 2,  ac = (tid & 3) << 2;   // A tile: 64 rows x 16 cols
    const int wr = tid >> 4,  wc = (tid & 15) << 2;  // W tile: 16 rows x 64 cols

    for (int p = 0; p < 2; p++) {
        const float* A = Aarr[p];
        const float* W = Warr[p];
        const int K = Karr[p];
        if (A == nullptr) continue;
        for (int k0 = 0; k0 < K; k0 += 16) {
            float4 av = *(const float4*)(A + (size_t)(bm + ar) * K + k0 + ac);
            As[ac + 0][ar] = av.x;
            As[ac + 1][ar] = av.y;
            As[ac + 2][ar] = av.z;
            As[ac + 3][ar] = av.w;
            *(float4*)(&Bs[wr][wc]) =
                *(const float4*)(W + (size_t)(k0 + wr) * N + bn + wc);
            __syncthreads();
            #pragma unroll
            for (int k = 0; k < 16; k++) {
                float4 a  = *(const float4*)(&As[k][ty << 2]);
                float4 bb = *(const float4*)(&Bs[k][tx << 2]);
                acc[0][0] += a.x * bb.x; acc[0][1] += a.x * bb.y;
                acc[0][2] += a.x * bb.z; acc[0][3] += a.x * bb.w;
                acc[1][0] += a.y * bb.x; acc[1][1] += a.y * bb.y;
                acc[1][2] += a.y * bb.z; acc[1][3] += a.y * bb.w;
                acc[2][0] += a.z * bb.x; acc[2][1] += a.z * bb.y;
                acc[2][2] += a.z * bb.z; acc[2][3] += a.z * bb.w;
                acc[3][0] += a.w * bb.x; acc[3][1] += a.w * bb.y;
                acc[3][2] += a.w * bb.z; acc[3][3] += a.w * bb.w;
            }
            __syncthreads();
        }
    }

    #pragma unroll
    for (int i = 0; i < 4; i++) {
        const int r = bm + (ty << 2) + i;
        float* crow = C + (size_t)r * N + bn + (tx << 2);
        #pragma unroll
        for (int j = 0; j < 4; j++) {
            const int cn = bn + (tx << 2) + j;
            float v = acc[i][j];
            if (bias0) v += bias0[cn];
            if (bias1) v += bias1[cn];
            crow[j] = v;
        }
    }
}

// ---------------- LSTM pointwise ---------------------------------------------
__global__ __launch_bounds__(256) void lstm_kernel() {
    const int idx = blockIdx.x * 256 + threadIdx.x;   // < B*H
    const int b = idx >> 9, n = idx & (H_ - 1);
    const float* g = g_gates + (size_t)b * (4 * H_);
    const float ig = g[n];
    const float fg = g[H_ + n];
    const float gg = g[2 * H_ + n];
    const float og = g[3 * H_ + n];
    const float si = 1.0f / (1.0f + expf(-ig));
    const float sf = 1.0f / (1.0f + expf(-fg));
    const float so = 1.0f / (1.0f + expf(-og));
    const float cn = sf * g_c[idx] + si * tanhf(gg);
    g_c[idx] = cn;
    g_h[idx] = so * tanhf(cn);
}

// ---------------- init: c=0, e=sos, EOS column of outputs --------------------
__global__ __launch_bounds__(256) void init_kernel(
    const float* __restrict__ sos,
    float* __restrict__ o_seq, float* __restrict__ o_probs,
    float* __restrict__ o_logp, float* __restrict__ o_ent)
{
    const int i = blockIdx.x * 256 + threadIdx.x;     // up to B*V
    if (i < B_ * H_) g_c[i] = 0.0f;
    if (i < B_ * E_) g_e[i] = sos[i & (E_ - 1)];
    if (i < B_) {
        o_seq[(size_t)i * LP1 + L_]  = 0.0f;
        o_logp[(size_t)i * LP1 + L_] = 0.0f;
        o_ent[(size_t)i * LP1 + L_]  = 0.0f;
    }
    if (i < B_ * V_) {
        const int b = i >> 11, v = i & (V_ - 1);
        o_probs[((size_t)b * LP1 + L_) * V_ + v] = 1.0f;
    }
}

// ---------------- log_softmax + entropy + gumbel argmax + embed gather -------
__global__ __launch_bounds__(256) void sample_kernel(
    const float* __restrict__ embedding,
    float* __restrict__ o_seq, float* __restrict__ o_probs,
    float* __restrict__ o_logp, float* __restrict__ o_ent,
    uint32_t sk0, uint32_t sk1, int t)
{
    const int b = blockIdx.x;
    const int tid = threadIdx.x;
    const float* row = g_logits + (size_t)b * V_;

    __shared__ float sred[256];
    __shared__ int   sidx[256];
    __shared__ int   ssym;

    float xs[8];
    float mx = -3.402823466e38f;
    #pragma unroll
    for (int i = 0; i < 8; i++) {
        xs[i] = row[tid + i * 256];
        mx = fmaxf(mx, xs[i]);
    }
    sred[tid] = mx; __syncthreads();
    for (int s = 128; s > 0; s >>= 1) {
        if (tid < s) sred[tid] = fmaxf(sred[tid], sred[tid + s]);
        __syncthreads();
    }
    mx = sred[0]; __syncthreads();

    float se = 0.0f;
    #pragma unroll
    for (int i = 0; i < 8; i++) { xs[i] -= mx; se += expf(xs[i]); }
    sred[tid] = se; __syncthreads();
    for (int s = 128; s > 0; s >>= 1) {
        if (tid < s) sred[tid] += sred[tid + s];
        __syncthreads();
    }
    se = sred[0]; __syncthreads();
    const float lse = logf(se);

    float* probs_row = o_probs + ((size_t)b * LP1 + t) * V_;

    float ent = 0.0f;
    float bestv = -3.402823466e38f;
    int   besti = V_;
    #pragma unroll
    for (int i = 0; i < 8; i++) {
        const int v = tid + i * 256;
        const float lsm = xs[i] - lse;
        const float p = expf(lsm);
        probs_row[v] = p;
        ent += p * lsm;

        uint32_t o0, o1, bits;
#if JAX_PARTITIONABLE
        tf2x32(sk0, sk1, 0u, (uint32_t)(b * V_ + v), &o0, &o1);
        bits = o0 ^ o1;
#else
        const uint32_t j = (uint32_t)(b * V_ + v);
        const uint32_t half = (uint32_t)(B_ * V_ / 2);
        if (j < half) { tf2x32(sk0, sk1, j, j + half, &o0, &o1); bits = o0; }
        else          { tf2x32(sk0, sk1, j - half, j, &o0, &o1); bits = o1; }
#endif
        // JAX uniform(minval=tiny, maxval=1): f in [0,1); u = f if f>0 else tiny
        const float f = __uint_as_float((bits >> 9) | 0x3f800000u) - 1.0f;
        const float u = (f == 0.0f) ? 1.1754943508222875e-38f : f;
        const float g = -logf(-logf(u));
        const float val = lsm + g;
        if (val > bestv) { bestv = val; besti = v; }
    }

    // entropy reduce
    sred[tid] = ent; __syncthreads();
    for (int s = 128; s > 0; s >>= 1) {
        if (tid < s) sred[tid] += sred[tid + s];
        __syncthreads();
    }
    const float entTot = sred[0]; __syncthreads();

    // argmax reduce (ties -> lowest index, matching jnp.argmax)
    sred[tid] = bestv; sidx[tid] = besti; __syncthreads();
    for (int s = 128; s > 0; s >>= 1) {
        if (tid < s) {
            const float v2 = sred[tid + s];
            const int   i2 = sidx[tid + s];
            if (v2 > sred[tid] || (v2 == sred[tid] && i2 < sidx[tid])) {
                sred[tid] = v2; sidx[tid] = i2;
            }
        }
        __syncthreads();
    }

    if (tid == 0) {
        const int sym = sidx[0];
        ssym = sym;
        o_ent[(size_t)b * LP1 + t]  = -entTot;
        o_seq[(size_t)b * LP1 + t]  = (float)sym;
        o_logp[(size_t)b * LP1 + t] = (row[sym] - mx) - lse;
    }
    __syncthreads();
    const int sym = ssym;
    for (int j = tid; j < E_; j += 256)
        g_e[(size_t)b * E_ + j] = embedding[(size_t)sym * E_ + j];
}

// ---------------- host launcher ----------------------------------------------
extern "C" void kernel_launch(void* const* d_in, const int* in_sizes, int n_in,
                              void* d_out, int out_size) {
    (void)in_sizes; (void)n_in; (void)out_size;
    const float* x        = (const float*)d_in[0];
    const float* agent_w  = (const float*)d_in[1];
    const float* agent_b  = (const float*)d_in[2];
    const float* sos      = (const float*)d_in[3];
    const float* embedding= (const float*)d_in[4];
    const float* w_ih     = (const float*)d_in[5];
    const float* w_hh     = (const float*)d_in[6];
    const float* b_ih     = (const float*)d_in[7];
    const float* b_hh     = (const float*)d_in[8];
    const float* out_w    = (const float*)d_in[9];
    const float* out_b    = (const float*)d_in[10];

    float *h, *c, *e, *gates, *logits;
    cudaGetSymbolAddress((void**)&h, g_h);
    cudaGetSymbolAddress((void**)&c, g_c);
    cudaGetSymbolAddress((void**)&e, g_e);
    cudaGetSymbolAddress((void**)&gates, g_gates);
    cudaGetSymbolAddress((void**)&logits, g_logits);
    (void)c; (void)e;

    // Subkey chain for jax.random.key(1): key, sk = split(key) each step.
    uint32_t skA[L_], skB[L_];
    uint32_t k0 = 0u, k1 = 1u;
    for (int t = 0; t < L_; t++) {
        uint32_t a0, a1, b0, b1;
#if JAX_PARTITIONABLE
        // foldlike split: keys[i] = threefry(key, (0, i)); new key = keys[0], sk = keys[1]
        tf2x32(k0, k1, 0u, 0u, &a0, &a1);
        tf2x32(k0, k1, 0u, 1u, &b0, &b1);
        skA[t] = b0; skB[t] = b1;
        k0 = a0; k1 = a1;
#else
        // original split: counts iota(4) halved -> pairs (0,2) and (1,3)
        tf2x32(k0, k1, 0u, 2u, &a0, &a1);
        tf2x32(k0, k1, 1u, 3u, &b0, &b1);
        skA[t] = a1; skB[t] = b1;
        k0 = a0; k1 = b0;
#endif
    }

    float* out = (float*)d_out;
    float* o_seq   = out;                                   // [B,33]
    float* o_probs = out + (size_t)B_ * LP1;                // [B,33,V]
    float* o_logp  = o_probs + (size_t)B_ * LP1 * V_;       // [B,33]
    float* o_ent   = o_logp + (size_t)B_ * LP1;             // [B,33]

    init_kernel<<<(B_ * V_ + 255) / 256, 256>>>(sos, o_seq, o_probs, o_logp, o_ent);

    // h0 = x @ agent_w + agent_b
    gemm_kernel<<<dim3(H_ / 64, B_ / 64), 256>>>(
        x, agent_w, IND, nullptr, nullptr, 0, agent_b, nullptr, h, H_);

    for (int t = 0; t < L_; t++) {
        // gates = e @ w_ih + h @ w_hh + b_ih + b_hh
        gemm_kernel<<<dim3(4 * H_ / 64, B_ / 64), 256>>>(
            e, w_ih, E_, h, w_hh, H_, b_ih, b_hh, gates, 4 * H_);
        lstm_kernel<<<B_ * H_ / 256, 256>>>();
        // logits = h @ out_w + out_b
        gemm_kernel<<<dim3(V_ / 64, B_ / 64), 256>>>(
            h, out_w, H_, nullptr, nullptr, 0, out_b, nullptr, logits, V_);
        sample_kernel<<<B_, 256>>>(embedding, o_seq, o_probs, o_logp, o_ent,
                                   skA[t], skB[t], t);
    }
}

// round 3
// speedup vs baseline: 2.4906x; 2.4906x over previous
#include <cuda_runtime.h>
#include <cstdint>
#include <cstddef>

static constexpr int B_   = 512;
static constexpr int H_   = 512;
static constexpr int E_   = 512;
static constexpr int V_   = 2048;
static constexpr int L_   = 32;
static constexpr int LP1  = 33;
static constexpr int IND  = 1024;
static constexpr int G4   = 4 * H_;   // 2048

// ---------------- persistent scratch (device globals; no allocation) ---------
__device__ float g_hbuf[2][B_ * H_];
__device__ float g_c[B_ * H_];
__device__ float g_logits[B_ * V_];
__device__ float g_EP[(V_ + 1) * G4];      // [2049, 2048] emb@w_ih (perm) + bias; row V_ = sos
__device__ float g_Wg[H_ * G4];            // permuted w_hh
__device__ float g_Wihp[E_ * G4];          // permuted w_ih
__device__ float g_biasg[G4];              // permuted b_ih+b_hh
__device__ int   g_sym[B_];

// ---------------- threefry2x32 (20 rounds), host+device ---------------------
__host__ __device__ __forceinline__ uint32_t rotl32(uint32_t x, int d) {
    return (x << d) | (x >> (32 - d));
}
__host__ __device__ inline void tf2x32(uint32_t k0, uint32_t k1,
                                       uint32_t x0, uint32_t x1,
                                       uint32_t* o0, uint32_t* o1) {
    const uint32_t ks0 = k0, ks1 = k1, ks2 = k0 ^ k1 ^ 0x1BD11BDAu;
    x0 += ks0; x1 += ks1;
    x0 += x1; x1 = rotl32(x1, 13); x1 ^= x0;
    x0 += x1; x1 = rotl32(x1, 15); x1 ^= x0;
    x0 += x1; x1 = rotl32(x1, 26); x1 ^= x0;
    x0 += x1; x1 = rotl32(x1, 6);  x1 ^= x0;
    x0 += ks1; x1 += ks2 + 1u;
    x0 += x1; x1 = rotl32(x1, 17); x1 ^= x0;
    x0 += x1; x1 = rotl32(x1, 29); x1 ^= x0;
    x0 += x1; x1 = rotl32(x1, 16); x1 ^= x0;
    x0 += x1; x1 = rotl32(x1, 24); x1 ^= x0;
    x0 += ks2; x1 += ks0 + 2u;
    x0 += x1; x1 = rotl32(x1, 13); x1 ^= x0;
    x0 += x1; x1 = rotl32(x1, 15); x1 ^= x0;
    x0 += x1; x1 = rotl32(x1, 26); x1 ^= x0;
    x0 += x1; x1 = rotl32(x1, 6);  x1 ^= x0;
    x0 += ks0; x1 += ks1 + 3u;
    x0 += x1; x1 = rotl32(x1, 17); x1 ^= x0;
    x0 += x1; x1 = rotl32(x1, 29); x1 ^= x0;
    x0 += x1; x1 = rotl32(x1, 16); x1 ^= x0;
    x0 += x1; x1 = rotl32(x1, 24); x1 ^= x0;
    x0 += ks1; x1 += ks2 + 4u;
    x0 += x1; x1 = rotl32(x1, 13); x1 ^= x0;
    x0 += x1; x1 = rotl32(x1, 15); x1 ^= x0;
    x0 += x1; x1 = rotl32(x1, 26); x1 ^= x0;
    x0 += x1; x1 = rotl32(x1, 6);  x1 ^= x0;
    x0 += ks2; x1 += ks0 + 5u;
    *o0 = x0; *o1 = x1;
}

// ---------------- GEMM (64x128 tile, BK=16, 256 thr, 8x4 microtile) ----------
// C[M,N] = A[M,K] @ W[K,N]; mode 0: +bias -> C. mode 1: fused LSTM epilogue
// (columns of W interleaved as 4n+g; gates += EP[sym[r]]; write c,h).
__global__ __launch_bounds__(256) void gemm_fused(
    const float* __restrict__ A, const float* __restrict__ W,
    int K, int N,
    const float* __restrict__ bias, float* __restrict__ C,
    const float* __restrict__ EP, const int* __restrict__ sym,
    float* __restrict__ c_state, float* __restrict__ h_out,
    int mode)
{
    __shared__ __align__(16) float As[16][68];
    __shared__ __align__(16) float Bs[16][128];
    const int tid = threadIdx.x;
    const int bn = blockIdx.x * 128, bm = blockIdx.y * 64;
    const int tx = tid & 31, ty = tid >> 5;
    const int r0 = ty * 8, c0 = tx * 4;

    const int arow = tid >> 2, acol = (tid & 3) << 2;
    const int wrow = tid >> 5, wcol = (tid & 31) << 2;

    const float* Aptr  = A + (size_t)(bm + arow) * K + acol;
    const float* Wptr0 = W + (size_t)wrow * N + bn + wcol;
    const float* Wptr1 = Wptr0 + (size_t)8 * N;

    float4 pa  = *(const float4*)(Aptr);
    float4 pb0 = *(const float4*)(Wptr0);
    float4 pb1 = *(const float4*)(Wptr1);

    float acc[8][4] = {};

    for (int k0 = 0; k0 < K; k0 += 16) {
        As[acol + 0][arow] = pa.x;
        As[acol + 1][arow] = pa.y;
        As[acol + 2][arow] = pa.z;
        As[acol + 3][arow] = pa.w;
        *(float4*)(&Bs[wrow][wcol])     = pb0;
        *(float4*)(&Bs[wrow + 8][wcol]) = pb1;
        __syncthreads();
        if (k0 + 16 < K) {
            pa  = *(const float4*)(Aptr + k0 + 16);
            pb0 = *(const float4*)(Wptr0 + (size_t)(k0 + 16) * N);
            pb1 = *(const float4*)(Wptr1 + (size_t)(k0 + 16) * N);
        }
        #pragma unroll
        for (int k = 0; k < 16; k++) {
            float4 a0 = *(const float4*)(&As[k][r0]);
            float4 a1 = *(const float4*)(&As[k][r0 + 4]);
            float4 b  = *(const float4*)(&Bs[k][c0]);
            float av[8] = {a0.x, a0.y, a0.z, a0.w, a1.x, a1.y, a1.z, a1.w};
            #pragma unroll
            for (int i = 0; i < 8; i++) {
                acc[i][0] += av[i] * b.x;
                acc[i][1] += av[i] * b.y;
                acc[i][2] += av[i] * b.z;
                acc[i][3] += av[i] * b.w;
            }
        }
        __syncthreads();
    }

    if (mode == 0) {
        float4 bv = make_float4(0.f, 0.f, 0.f, 0.f);
        if (bias) bv = *(const float4*)(bias + bn + c0);
        #pragma unroll
        for (int i = 0; i < 8; i++) {
            const int r = bm + r0 + i;
            float4 v;
            v.x = acc[i][0] + bv.x;
            v.y = acc[i][1] + bv.y;
            v.z = acc[i][2] + bv.z;
            v.w = acc[i][3] + bv.w;
            *(float4*)(C + (size_t)r * N + bn + c0) = v;
        }
    } else {
        const int n = (bn + c0) >> 2;
        #pragma unroll
        for (int i = 0; i < 8; i++) {
            const int r = bm + r0 + i;
            const int s = __ldg(sym + r);
            const float4 ep = *(const float4*)(EP + (size_t)s * G4 + bn + c0);
            const float gi = acc[i][0] + ep.x;
            const float gf = acc[i][1] + ep.y;
            const float gg = acc[i][2] + ep.z;
            const float go = acc[i][3] + ep.w;
            const float si = 1.0f / (1.0f + expf(-gi));
            const float sf = 1.0f / (1.0f + expf(-gf));
            const float so = 1.0f / (1.0f + expf(-go));
            const float tg = tanhf(gg);
            const size_t idx = (size_t)r * H_ + n;
            const float cn = sf * c_state[idx] + si * tg;
            c_state[idx] = cn;
            h_out[idx] = so * tanhf(cn);
        }
    }
}

// ---------------- permute weights (interleave gate columns) ------------------
__global__ __launch_bounds__(256) void permute_kernel(
    const float* __restrict__ w_hh, const float* __restrict__ w_ih,
    const float* __restrict__ b_ih, const float* __restrict__ b_hh)
{
    const int idx = blockIdx.x * 256 + threadIdx.x;  // < 512*2048
    const int k = idx >> 11, col = idx & (G4 - 1);
    const int n = col >> 2, g = col & 3;
    const int src = g * H_ + n;
    g_Wg[idx]   = w_hh[(size_t)k * G4 + src];
    g_Wihp[idx] = w_ih[(size_t)k * G4 + src];
    if (idx < G4) g_biasg[idx] = b_ih[src] + b_hh[src];
}

// ---------------- sos row of EP ----------------------------------------------
__global__ __launch_bounds__(256) void sosrow_kernel(const float* __restrict__ sos) {
    const int c = blockIdx.x * 256 + threadIdx.x;    // < 2048
    float acc = g_biasg[c];
    for (int k = 0; k < E_; k++)
        acc += sos[k] * g_Wihp[(size_t)k * G4 + c];
    g_EP[(size_t)V_ * G4 + c] = acc;
}

// ---------------- init: c=0, sym=sos, EOS column of outputs ------------------
__global__ __launch_bounds__(256) void init_kernel(
    float* __restrict__ o_seq, float* __restrict__ o_probs,
    float* __restrict__ o_logp, float* __restrict__ o_ent)
{
    const int i = blockIdx.x * 256 + threadIdx.x;     // up to B*V
    if (i < B_ * H_) g_c[i] = 0.0f;
    if (i < B_) {
        g_sym[i] = V_;   // sos row
        o_seq[(size_t)i * LP1 + L_]  = 0.0f;
        o_logp[(size_t)i * LP1 + L_] = 0.0f;
        o_ent[(size_t)i * LP1 + L_]  = 0.0f;
    }
    if (i < B_ * V_) {
        const int b = i >> 11, v = i & (V_ - 1);
        o_probs[((size_t)b * LP1 + L_) * V_ + v] = 1.0f;
    }
}

// ---------------- log_softmax + entropy + gumbel argmax ----------------------
__global__ __launch_bounds__(256) void sample_kernel(
    float* __restrict__ o_seq, float* __restrict__ o_probs,
    float* __restrict__ o_logp, float* __restrict__ o_ent,
    uint32_t sk0, uint32_t sk1, int t)
{
    const int b = blockIdx.x;
    const int tid = threadIdx.x;
    const float* row = g_logits + (size_t)b * V_;

    __shared__ float sred[256];
    __shared__ int   sidx[256];

    float xs[8];
    float mx = -3.402823466e38f;
    #pragma unroll
    for (int i = 0; i < 8; i++) {
        xs[i] = row[tid + i * 256];
        mx = fmaxf(mx, xs[i]);
    }
    sred[tid] = mx; __syncthreads();
    for (int s = 128; s > 0; s >>= 1) {
        if (tid < s) sred[tid] = fmaxf(sred[tid], sred[tid + s]);
        __syncthreads();
    }
    mx = sred[0]; __syncthreads();

    float se = 0.0f;
    #pragma unroll
    for (int i = 0; i < 8; i++) { xs[i] -= mx; se += expf(xs[i]); }
    sred[tid] = se; __syncthreads();
    for (int s = 128; s > 0; s >>= 1) {
        if (tid < s) sred[tid] += sred[tid + s];
        __syncthreads();
    }
    se = sred[0]; __syncthreads();
    const float lse = logf(se);

    float* probs_row = o_probs + ((size_t)b * LP1 + t) * V_;

    float ent = 0.0f;
    float bestv = -3.402823466e38f;
    int   besti = V_;
    #pragma unroll
    for (int i = 0; i < 8; i++) {
        const int v = tid + i * 256;
        const float lsm = xs[i] - lse;
        const float p = expf(lsm);
        probs_row[v] = p;
        ent += p * lsm;

        uint32_t o0, o1;
        tf2x32(sk0, sk1, 0u, (uint32_t)(b * V_ + v), &o0, &o1);
        const uint32_t bits = o0 ^ o1;
        const float f = __uint_as_float((bits >> 9) | 0x3f800000u) - 1.0f;
        const float u = (f == 0.0f) ? 1.1754943508222875e-38f : f;
        const float g = -logf(-logf(u));
        const float val = lsm + g;
        if (val > bestv) { bestv = val; besti = v; }
    }

    sred[tid] = ent; __syncthreads();
    for (int s = 128; s > 0; s >>= 1) {
        if (tid < s) sred[tid] += sred[tid + s];
        __syncthreads();
    }
    const float entTot = sred[0]; __syncthreads();

    sred[tid] = bestv; sidx[tid] = besti; __syncthreads();
    for (int s = 128; s > 0; s >>= 1) {
        if (tid < s) {
            const float v2 = sred[tid + s];
            const int   i2 = sidx[tid + s];
            if (v2 > sred[tid] || (v2 == sred[tid] && i2 < sidx[tid])) {
                sred[tid] = v2; sidx[tid] = i2;
            }
        }
        __syncthreads();
    }

    if (tid == 0) {
        const int sym = sidx[0];
        g_sym[b] = sym;
        o_ent[(size_t)b * LP1 + t]  = -entTot;
        o_seq[(size_t)b * LP1 + t]  = (float)sym;
        o_logp[(size_t)b * LP1 + t] = (row[sym] - mx) - lse;
    }
}

// ---------------- host launcher ----------------------------------------------
extern "C" void kernel_launch(void* const* d_in, const int* in_sizes, int n_in,
                              void* d_out, int out_size) {
    (void)in_sizes; (void)n_in; (void)out_size;
    const float* x        = (const float*)d_in[0];
    const float* agent_w  = (const float*)d_in[1];
    const float* agent_b  = (const float*)d_in[2];
    const float* sos      = (const float*)d_in[3];
    const float* embedding= (const float*)d_in[4];
    const float* w_ih     = (const float*)d_in[5];
    const float* w_hh     = (const float*)d_in[6];
    const float* b_ih     = (const float*)d_in[7];
    const float* b_hh     = (const float*)d_in[8];
    const float* out_w    = (const float*)d_in[9];
    const float* out_b    = (const float*)d_in[10];

    float *hbuf, *c, *logits, *EP, *Wg, *Wihp, *biasg;
    int* sym;
    cudaGetSymbolAddress((void**)&hbuf, g_hbuf);
    cudaGetSymbolAddress((void**)&c, g_c);
    cudaGetSymbolAddress((void**)&logits, g_logits);
    cudaGetSymbolAddress((void**)&EP, g_EP);
    cudaGetSymbolAddress((void**)&Wg, g_Wg);
    cudaGetSymbolAddress((void**)&Wihp, g_Wihp);
    cudaGetSymbolAddress((void**)&biasg, g_biasg);
    cudaGetSymbolAddress((void**)&sym, g_sym);
    float* h0buf = hbuf;
    float* h1buf = hbuf + (size_t)B_ * H_;

    // Subkey chain for jax.random.key(1) (partitionable threefry).
    uint32_t skA[L_], skB[L_];
    uint32_t k0 = 0u, k1 = 1u;
    for (int t = 0; t < L_; t++) {
        uint32_t a0, a1, b0, b1;
        tf2x32(k0, k1, 0u, 0u, &a0, &a1);
        tf2x32(k0, k1, 0u, 1u, &b0, &b1);
        skA[t] = b0; skB[t] = b1;
        k0 = a0; k1 = a1;
    }

    float* out = (float*)d_out;
    float* o_seq   = out;                                   // [B,33]
    float* o_probs = out + (size_t)B_ * LP1;                // [B,33,V]
    float* o_logp  = o_probs + (size_t)B_ * LP1 * V_;       // [B,33]
    float* o_ent   = o_logp + (size_t)B_ * LP1;             // [B,33]

    init_kernel<<<(B_ * V_ + 255) / 256, 256>>>(o_seq, o_probs, o_logp, o_ent);
    permute_kernel<<<(H_ * G4 + 255) / 256, 256>>>(w_hh, w_ih, b_ih, b_hh);
    sosrow_kernel<<<G4 / 256, 256>>>(sos);

    // EP = embedding @ Wihp + biasg   [V, 4H]
    gemm_fused<<<dim3(G4 / 128, V_ / 64), 256>>>(
        embedding, Wihp, E_, G4, biasg, EP,
        nullptr, nullptr, nullptr, nullptr, 0);

    // h0 = x @ agent_w + agent_b
    gemm_fused<<<dim3(H_ / 128, B_ / 64), 256>>>(
        x, agent_w, IND, H_, agent_b, h0buf,
        nullptr, nullptr, nullptr, nullptr, 0);

    for (int t = 0; t < L_; t++) {
        float* h_in  = (t & 1) ? h1buf : h0buf;
        float* h_out = (t & 1) ? h0buf : h1buf;
        // gates = h_in @ Wg + EP[sym]  -> fused LSTM -> c, h_out
        gemm_fused<<<dim3(G4 / 128, B_ / 64), 256>>>(
            h_in, Wg, H_, G4, nullptr, nullptr,
            EP, sym, c, h_out, 1);
        // logits = h_out @ out_w + out_b
        gemm_fused<<<dim3(V_ / 128, B_ / 64), 256>>>(
            h_out, out_w, H_, V_, out_b, logits,
            nullptr, nullptr, nullptr, nullptr, 0);
        sample_kernel<<<B_, 256>>>(o_seq, o_probs, o_logp, o_ent,
                                   skA[t], skB[t], t);
    }
}

// round 5
// speedup vs baseline: 2.7520x; 1.1049x over previous
#include <cuda_runtime.h>
#include <cuda_bf16.h>
#include <cstdint>
#include <cstddef>

static constexpr int B_   = 512;
static constexpr int H_   = 512;
static constexpr int E_   = 512;
static constexpr int V_   = 2048;
static constexpr int L_   = 32;
static constexpr int LP1  = 33;
static constexpr int IND  = 1024;
static constexpr int G4   = 4 * H_;   // 2048
static constexpr int K6   = 6 * H_;   // 3072 (bf16x6 folded K)

// ---------------- persistent scratch (device globals; no allocation) ---------
__device__ float g_c[B_ * H_];
__device__ float g_h0[B_ * H_];
__device__ float g_logits[B_ * V_];
__device__ float g_EP[(V_ + 1) * G4];      // [2049,2048] emb@w_ih(perm)+bias; row V_=sos
__device__ float g_Wihp[E_ * G4];
__device__ float g_biasg[G4];
__device__ int   g_sym[B_];
__device__ __nv_bfloat16 g_h6[2][B_ * K6];     // split h [512,3072]
__device__ __nv_bfloat16 g_W6g[G4 * K6];       // split+interleaved w_hh^T [2048,3072]
__device__ __nv_bfloat16 g_W6o[V_ * K6];       // split out_w^T [2048,3072]

// ---------------- threefry2x32 (20 rounds), host+device ---------------------
__host__ __device__ __forceinline__ uint32_t rotl32(uint32_t x, int d) {
    return (x << d) | (x >> (32 - d));
}
__host__ __device__ inline void tf2x32(uint32_t k0, uint32_t k1,
                                       uint32_t x0, uint32_t x1,
                                       uint32_t* o0, uint32_t* o1) {
    const uint32_t ks0 = k0, ks1 = k1, ks2 = k0 ^ k1 ^ 0x1BD11BDAu;
    x0 += ks0; x1 += ks1;
    x0 += x1; x1 = rotl32(x1, 13); x1 ^= x0;
    x0 += x1; x1 = rotl32(x1, 15); x1 ^= x0;
    x0 += x1; x1 = rotl32(x1, 26); x1 ^= x0;
    x0 += x1; x1 = rotl32(x1, 6);  x1 ^= x0;
    x0 += ks1; x1 += ks2 + 1u;
    x0 += x1; x1 = rotl32(x1, 17); x1 ^= x0;
    x0 += x1; x1 = rotl32(x1, 29); x1 ^= x0;
    x0 += x1; x1 = rotl32(x1, 16); x1 ^= x0;
    x0 += x1; x1 = rotl32(x1, 24); x1 ^= x0;
    x0 += ks2; x1 += ks0 + 2u;
    x0 += x1; x1 = rotl32(x1, 13); x1 ^= x0;
    x0 += x1; x1 = rotl32(x1, 15); x1 ^= x0;
    x0 += x1; x1 = rotl32(x1, 26); x1 ^= x0;
    x0 += x1; x1 = rotl32(x1, 6);  x1 ^= x0;
    x0 += ks0; x1 += ks1 + 3u;
    x0 += x1; x1 = rotl32(x1, 17); x1 ^= x0;
    x0 += x1; x1 = rotl32(x1, 29); x1 ^= x0;
    x0 += x1; x1 = rotl32(x1, 16); x1 ^= x0;
    x0 += x1; x1 = rotl32(x1, 24); x1 ^= x0;
    x0 += ks1; x1 += ks2 + 4u;
    x0 += x1; x1 = rotl32(x1, 13); x1 ^= x0;
    x0 += x1; x1 = rotl32(x1, 15); x1 ^= x0;
    x0 += x1; x1 = rotl32(x1, 26); x1 ^= x0;
    x0 += x1; x1 = rotl32(x1, 6);  x1 ^= x0;
    x0 += ks2; x1 += ks0 + 5u;
    *o0 = x0; *o1 = x1;
}

// ---------------- small PTX wrappers (sm_80-compatible) ----------------------
__device__ __forceinline__ uint32_t smem_u32(const void* p) {
    uint32_t a;
    asm("{ .reg .u64 t; cvta.to.shared.u64 t, %1; cvt.u32.u64 %0, t; }"
        : "=r"(a) : "l"(p));
    return a;
}
__device__ __forceinline__ void cpasync16(uint32_t saddr, const void* g) {
    asm volatile("cp.async.cg.shared.global [%0], [%1], 16;" :: "r"(saddr), "l"(g));
}
__device__ __forceinline__ void cp_commit() {
    asm volatile("cp.async.commit_group;" ::: "memory");
}
template <int N>
__device__ __forceinline__ void cp_wait() {
    asm volatile("cp.async.wait_group %0;" :: "n"(N) : "memory");
}
__device__ __forceinline__ void ldsm4(uint32_t* r, uint32_t addr) {
    asm volatile("ldmatrix.sync.aligned.m8n8.x4.shared.b16 {%0,%1,%2,%3}, [%4];"
        : "=r"(r[0]), "=r"(r[1]), "=r"(r[2]), "=r"(r[3]) : "r"(addr));
}
__device__ __forceinline__ void mma16816(float* d, const uint32_t* a, const uint32_t* b) {
    asm volatile(
        "mma.sync.aligned.m16n8k16.row.col.f32.bf16.bf16.f32 "
        "{%0,%1,%2,%3}, {%4,%5,%6,%7}, {%8,%9}, {%0,%1,%2,%3};"
        : "+f"(d[0]), "+f"(d[1]), "+f"(d[2]), "+f"(d[3])
        : "r"(a[0]), "r"(a[1]), "r"(a[2]), "r"(a[3]), "r"(b[0]), "r"(b[1]));
}

// ---------------- bf16 split helpers -----------------------------------------
__host__ __device__ __forceinline__ uint32_t packbf(__nv_bfloat16 lo, __nv_bfloat16 hi) {
    return (uint32_t)__bfloat16_as_ushort(lo) | ((uint32_t)__bfloat16_as_ushort(hi) << 16);
}
__device__ __forceinline__ void split3(float a, __nv_bfloat16& a0,
                                       __nv_bfloat16& a1, __nv_bfloat16& a2) {
    a0 = __float2bfloat16_rn(a);
    float r = a - __bfloat162float(a0);
    a1 = __float2bfloat16_rn(r);
    float r2 = r - __bfloat162float(a1);
    a2 = __float2bfloat16_rn(r2);
}

// ============================================================================
// HMMA GEMM: out[512, 2048] = A6[512,3072] x W6[2048,3072]^T (bf16, f32 acc)
// CTA 64x128, BK=64, 256 thr (2x4 warps, 32x32 warp tile), cp.async double-buf.
// mode 0: +bias -> out. mode 1: LSTM epilogue via SMEM transpose.
// ============================================================================
static constexpr int BM = 64, BN = 128, BK = 64;
static constexpr int NCHUNK = K6 / BK;    // 48
static constexpr int ASTG = BM * BK * 2;  // 8192
static constexpr int BSTG = BN * BK * 2;  // 16384

__global__ __launch_bounds__(256, 1) void mma_gemm(
    const __nv_bfloat16* __restrict__ A6, const __nv_bfloat16* __restrict__ W6,
    const float* __restrict__ EP, const int* __restrict__ sym,
    float* __restrict__ c_state, __nv_bfloat16* __restrict__ h6out,
    const float* __restrict__ bias, float* __restrict__ out, int mode)
{
    __shared__ __align__(16) union {
        struct { uint8_t A[2][ASTG]; uint8_t B[2][BSTG]; } t;   // 49152
        float epi[64][132];                                      // 33792
    } sm;

    const int tid = threadIdx.x;
    const int wid = tid >> 5, lane = tid & 31;
    const int wm = wid & 1, wn = wid >> 1;
    const int bn = blockIdx.x * BN, bm = blockIdx.y * BM;

    const uint32_t sA = smem_u32(&sm.t.A[0][0]);
    const uint32_t sB = smem_u32(&sm.t.B[0][0]);

    // ldmatrix lane geometry
    const int rA = wm * 32 + (lane & 7) + ((lane >> 3) & 1) * 8;  // + mi*16
    const int cbA = lane >> 4;
    const int rB = wn * 32 + ((lane >> 4) << 3) + (lane & 7);     // + half*16
    const int cbB = (lane >> 3) & 1;

    // cp.async geometry
    int aRow[2], aCol[2]; uint32_t aS[2];
    #pragma unroll
    for (int i = 0; i < 2; i++) {
        const int s = tid + i * 256;          // < 512
        aRow[i] = s >> 3; aCol[i] = s & 7;
        aS[i] = (uint32_t)(aRow[i] * 128 + ((aCol[i] ^ (aRow[i] & 7)) << 4));
    }
    int bRow[4], bCol[4]; uint32_t bS[4];
    #pragma unroll
    for (int i = 0; i < 4; i++) {
        const int s = tid + i * 256;          // < 1024
        bRow[i] = s >> 3; bCol[i] = s & 7;
        bS[i] = (uint32_t)(bRow[i] * 128 + ((bCol[i] ^ (bRow[i] & 7)) << 4));
    }

    float acc[2][4][4] = {};

    // prefetch chunk 0
    {
        #pragma unroll
        for (int i = 0; i < 2; i++)
            cpasync16(sA + aS[i], A6 + (size_t)(bm + aRow[i]) * K6 + aCol[i] * 8);
        #pragma unroll
        for (int i = 0; i < 4; i++)
            cpasync16(sB + bS[i], W6 + (size_t)(bn + bRow[i]) * K6 + bCol[i] * 8);
        cp_commit();
    }

    for (int ck = 0; ck < NCHUNK; ck++) {
        const int buf = ck & 1;
        if (ck + 1 < NCHUNK) {
            const int nb = (ck + 1) & 1;
            const size_t koff = (size_t)(ck + 1) * BK;
            #pragma unroll
            for (int i = 0; i < 2; i++)
                cpasync16(sA + nb * ASTG + aS[i],
                          A6 + (size_t)(bm + aRow[i]) * K6 + koff + aCol[i] * 8);
            #pragma unroll
            for (int i = 0; i < 4; i++)
                cpasync16(sB + nb * BSTG + bS[i],
                          W6 + (size_t)(bn + bRow[i]) * K6 + koff + bCol[i] * 8);
            cp_commit();
            cp_wait<1>();
        } else {
            cp_wait<0>();
        }
        __syncthreads();

        const uint32_t Ab = sA + buf * ASTG;
        const uint32_t Bb = sB + buf * BSTG;
        #pragma unroll
        for (int s = 0; s < 4; s++) {
            uint32_t afr[2][4];
            #pragma unroll
            for (int mi = 0; mi < 2; mi++) {
                const int row = rA + mi * 16;
                ldsm4(afr[mi], Ab + row * 128 + (((2 * s + cbA) ^ (row & 7)) << 4));
            }
            uint32_t bfr[4][2];
            #pragma unroll
            for (int half = 0; half < 2; half++) {
                uint32_t q[4];
                const int row = rB + half * 16;
                ldsm4(q, Bb + row * 128 + (((2 * s + cbB) ^ (row & 7)) << 4));
                bfr[2 * half][0] = q[0]; bfr[2 * half][1] = q[1];
                bfr[2 * half + 1][0] = q[2]; bfr[2 * half + 1][1] = q[3];
            }
            #pragma unroll
            for (int mi = 0; mi < 2; mi++)
                #pragma unroll
                for (int ni = 0; ni < 4; ni++)
                    mma16816(acc[mi][ni], afr[mi], bfr[ni]);
        }
        __syncthreads();
    }

    if (mode == 0) {
        #pragma unroll
        for (int mi = 0; mi < 2; mi++) {
            const int R0 = bm + wm * 32 + mi * 16 + (lane >> 2);
            #pragma unroll
            for (int ni = 0; ni < 4; ni++) {
                const int C0 = bn + wn * 32 + ni * 8 + 2 * (lane & 3);
                const float b0 = bias[C0], b1 = bias[C0 + 1];
                float2 v0 = make_float2(acc[mi][ni][0] + b0, acc[mi][ni][1] + b1);
                float2 v1 = make_float2(acc[mi][ni][2] + b0, acc[mi][ni][3] + b1);
                *(float2*)(out + (size_t)R0 * V_ + C0) = v0;
                *(float2*)(out + (size_t)(R0 + 8) * V_ + C0) = v1;
            }
        }
    } else {
        // dump frags to SMEM, then LSTM per unit
        #pragma unroll
        for (int mi = 0; mi < 2; mi++) {
            const int r0 = wm * 32 + mi * 16 + (lane >> 2);
            #pragma unroll
            for (int ni = 0; ni < 4; ni++) {
                const int c0 = wn * 32 + ni * 8 + 2 * (lane & 3);
                sm.epi[r0][c0]     = acc[mi][ni][0];
                sm.epi[r0][c0 + 1] = acc[mi][ni][1];
                sm.epi[r0 + 8][c0]     = acc[mi][ni][2];
                sm.epi[r0 + 8][c0 + 1] = acc[mi][ni][3];
            }
        }
        __syncthreads();
        const int r = tid >> 2;                 // 0..63
        const int nl0 = (tid & 3) * 8;          // 8 units per thread
        const int R = bm + r;
        const int s = __ldg(sym + R);
        const float* eprow = EP + (size_t)s * G4;
        #pragma unroll
        for (int j = 0; j < 8; j++) {
            const int nl = nl0 + j;
            const int col4 = bn + 4 * nl;
            const float4 ep = *(const float4*)(eprow + col4);
            const float gi = sm.epi[r][4 * nl + 0] + ep.x;
            const float gf = sm.epi[r][4 * nl + 1] + ep.y;
            const float gg = sm.epi[r][4 * nl + 2] + ep.z;
            const float go = sm.epi[r][4 * nl + 3] + ep.w;
            const float si = 1.0f / (1.0f + expf(-gi));
            const float sf = 1.0f / (1.0f + expf(-gf));
            const float so = 1.0f / (1.0f + expf(-go));
            const int ng = (bn >> 2) + nl;
            const size_t idx = (size_t)R * H_ + ng;
            const float cn = sf * c_state[idx] + si * tanhf(gg);
            c_state[idx] = cn;
            const float h = so * tanhf(cn);
            __nv_bfloat16 a0, a1, a2;
            split3(h, a0, a1, a2);
            uint32_t* o = (uint32_t*)h6out + (size_t)R * (K6 / 2) + 3 * ng;
            o[0] = packbf(a0, a0);
            o[1] = packbf(a1, a1);
            o[2] = packbf(a2, a0);
        }
    }
}

// ---------------- SIMT fp32 GEMM (prep only: EP, h0) -------------------------
__global__ __launch_bounds__(256) void gemm_f32(
    const float* __restrict__ A, const float* __restrict__ W,
    int K, int N, const float* __restrict__ bias, float* __restrict__ C)
{
    __shared__ __align__(16) float As[16][68];
    __shared__ __align__(16) float Bs[16][128];
    const int tid = threadIdx.x;
    const int bn = blockIdx.x * 128, bm = blockIdx.y * 64;
    const int tx = tid & 31, ty = tid >> 5;
    const int r0 = ty * 8, c0 = tx * 4;
    const int arow = tid >> 2, acol = (tid & 3) << 2;
    const int wrow = tid >> 5, wcol = (tid & 31) << 2;

    const float* Aptr  = A + (size_t)(bm + arow) * K + acol;
    const float* Wptr0 = W + (size_t)wrow * N + bn + wcol;
    const float* Wptr1 = Wptr0 + (size_t)8 * N;
    float4 pa  = *(const float4*)(Aptr);
    float4 pb0 = *(const float4*)(Wptr0);
    float4 pb1 = *(const float4*)(Wptr1);
    float acc[8][4] = {};
    for (int k0 = 0; k0 < K; k0 += 16) {
        As[acol + 0][arow] = pa.x; As[acol + 1][arow] = pa.y;
        As[acol + 2][arow] = pa.z; As[acol + 3][arow] = pa.w;
        *(float4*)(&Bs[wrow][wcol])     = pb0;
        *(float4*)(&Bs[wrow + 8][wcol]) = pb1;
        __syncthreads();
        if (k0 + 16 < K) {
            pa  = *(const float4*)(Aptr + k0 + 16);
            pb0 = *(const float4*)(Wptr0 + (size_t)(k0 + 16) * N);
            pb1 = *(const float4*)(Wptr1 + (size_t)(k0 + 16) * N);
        }
        #pragma unroll
        for (int k = 0; k < 16; k++) {
            float4 a0 = *(const float4*)(&As[k][r0]);
            float4 a1 = *(const float4*)(&As[k][r0 + 4]);
            float4 b  = *(const float4*)(&Bs[k][c0]);
            float av[8] = {a0.x, a0.y, a0.z, a0.w, a1.x, a1.y, a1.z, a1.w};
            #pragma unroll
            for (int i = 0; i < 8; i++) {
                acc[i][0] += av[i] * b.x; acc[i][1] += av[i] * b.y;
                acc[i][2] += av[i] * b.z; acc[i][3] += av[i] * b.w;
            }
        }
        __syncthreads();
    }
    float4 bv = make_float4(0.f, 0.f, 0.f, 0.f);
    if (bias) bv = *(const float4*)(bias + bn + c0);
    #pragma unroll
    for (int i = 0; i < 8; i++) {
        const int rr = bm + r0 + i;
        float4 v;
        v.x = acc[i][0] + bv.x; v.y = acc[i][1] + bv.y;
        v.z = acc[i][2] + bv.z; v.w = acc[i][3] + bv.w;
        *(float4*)(C + (size_t)rr * N + bn + c0) = v;
    }
}

// ---------------- weight / state prep ----------------------------------------
__global__ __launch_bounds__(256) void permute_kernel(
    const float* __restrict__ w_ih, const float* __restrict__ b_ih,
    const float* __restrict__ b_hh)
{
    const int idx = blockIdx.x * 256 + threadIdx.x;  // < 512*2048
    const int k = idx >> 11, col = idx & (G4 - 1);
    const int n = col >> 2, g = col & 3;
    const int src = g * H_ + n;
    g_Wihp[idx] = w_ih[(size_t)k * G4 + src];
    if (idx < G4) g_biasg[idx] = b_ih[src] + b_hh[src];
}

__global__ __launch_bounds__(256) void build_w6(
    const float* __restrict__ W, __nv_bfloat16* __restrict__ out, int interleave)
{
    const int idx = blockIdx.x * 256 + threadIdx.x;  // < 2048*512
    const int k = idx >> 11, ncol = idx & (G4 - 1);
    const int src = interleave ? ((ncol & 3) * H_ + (ncol >> 2)) : ncol;
    const float w = W[(size_t)k * 2048 + src];
    __nv_bfloat16 b0, b1, b2;
    split3(w, b0, b1, b2);
    uint32_t* o = (uint32_t*)out + (size_t)ncol * (K6 / 2) + 3 * k;
    o[0] = packbf(b0, b1);   // j0:b0 j1:b1
    o[1] = packbf(b0, b1);   // j2:b0 j3:b1
    o[2] = packbf(b0, b2);   // j4:b0 j5:b2
}

__global__ __launch_bounds__(256) void split_h0_kernel() {
    const int idx = blockIdx.x * 256 + threadIdx.x;  // < 512*512
    const int r = idx >> 9, n = idx & (H_ - 1);
    __nv_bfloat16 a0, a1, a2;
    split3(g_h0[idx], a0, a1, a2);
    uint32_t* o = (uint32_t*)g_h6[0] + (size_t)r * (K6 / 2) + 3 * n;
    o[0] = packbf(a0, a0);   // j0:a0 j1:a0
    o[1] = packbf(a1, a1);   // j2:a1 j3:a1
    o[2] = packbf(a2, a0);   // j4:a2 j5:a0
}

__global__ __launch_bounds__(256) void sosrow_kernel(const float* __restrict__ sos) {
    const int c = blockIdx.x * 256 + threadIdx.x;    // < 2048
    float acc = g_biasg[c];
    for (int k = 0; k < E_; k++)
        acc += sos[k] * g_Wihp[(size_t)k * G4 + c];
    g_EP[(size_t)V_ * G4 + c] = acc;
}

__global__ __launch_bounds__(256) void init_kernel(
    float* __restrict__ o_seq, float* __restrict__ o_probs,
    float* __restrict__ o_logp, float* __restrict__ o_ent)
{
    const int i = blockIdx.x * 256 + threadIdx.x;
    if (i < B_ * H_) g_c[i] = 0.0f;
    if (i < B_) {
        g_sym[i] = V_;
        o_seq[(size_t)i * LP1 + L_]  = 0.0f;
        o_logp[(size_t)i * LP1 + L_] = 0.0f;
        o_ent[(size_t)i * LP1 + L_]  = 0.0f;
    }
    if (i < B_ * V_) {
        const int b = i >> 11, v = i & (V_ - 1);
        o_probs[((size_t)b * LP1 + L_) * V_ + v] = 1.0f;
    }
}

// ---------------- log_softmax + entropy + gumbel argmax ----------------------
__global__ __launch_bounds__(256) void sample_kernel(
    float* __restrict__ o_seq, float* __restrict__ o_probs,
    float* __restrict__ o_logp, float* __restrict__ o_ent,
    uint32_t sk0, uint32_t sk1, int t)
{
    const int b = blockIdx.x;
    const int tid = threadIdx.x;
    const float* row = g_logits + (size_t)b * V_;

    __shared__ float sred[256];
    __shared__ int   sidx[256];

    float xs[8];
    float mx = -3.402823466e38f;
    #pragma unroll
    for (int i = 0; i < 8; i++) {
        xs[i] = row[tid + i * 256];
        mx = fmaxf(mx, xs[i]);
    }
    sred[tid] = mx; __syncthreads();
    for (int s = 128; s > 0; s >>= 1) {
        if (tid < s) sred[tid] = fmaxf(sred[tid], sred[tid + s]);
        __syncthreads();
    }
    mx = sred[0]; __syncthreads();

    float se = 0.0f;
    #pragma unroll
    for (int i = 0; i < 8; i++) { xs[i] -= mx; se += expf(xs[i]); }
    sred[tid] = se; __syncthreads();
    for (int s = 128; s > 0; s >>= 1) {
        if (tid < s) sred[tid] += sred[tid + s];
        __syncthreads();
    }
    se = sred[0]; __syncthreads();
    const float lse = logf(se);

    float* probs_row = o_probs + ((size_t)b * LP1 + t) * V_;
    float ent = 0.0f;
    float bestv = -3.402823466e38f;
    int   besti = V_;
    #pragma unroll
    for (int i = 0; i < 8; i++) {
        const int v = tid + i * 256;
        const float lsm = xs[i] - lse;
        const float p = expf(lsm);
        probs_row[v] = p;
        ent += p * lsm;
        uint32_t o0, o1;
        tf2x32(sk0, sk1, 0u, (uint32_t)(b * V_ + v), &o0, &o1);
        const uint32_t bits = o0 ^ o1;
        const float f = __uint_as_float((bits >> 9) | 0x3f800000u) - 1.0f;
        const float u = (f == 0.0f) ? 1.1754943508222875e-38f : f;
        const float g = -logf(-logf(u));
        const float val = lsm + g;
        if (val > bestv) { bestv = val; besti = v; }
    }

    sred[tid] = ent; __syncthreads();
    for (int s = 128; s > 0; s >>= 1) {
        if (tid < s) sred[tid] += sred[tid + s];
        __syncthreads();
    }
    const float entTot = sred[0]; __syncthreads();

    sred[tid] = bestv; sidx[tid] = besti; __syncthreads();
    for (int s = 128; s > 0; s >>= 1) {
        if (tid < s) {
            const float v2 = sred[tid + s];
            const int   i2 = sidx[tid + s];
            if (v2 > sred[tid] || (v2 == sred[tid] && i2 < sidx[tid])) {
                sred[tid] = v2; sidx[tid] = i2;
            }
        }
        __syncthreads();
    }
    if (tid == 0) {
        const int sym = sidx[0];
        g_sym[b] = sym;
        o_ent[(size_t)b * LP1 + t]  = -entTot;
        o_seq[(size_t)b * LP1 + t]  = (float)sym;
        o_logp[(size_t)b * LP1 + t] = (row[sym] - mx) - lse;
    }
}

// ---------------- host launcher ----------------------------------------------
extern "C" void kernel_launch(void* const* d_in, const int* in_sizes, int n_in,
                              void* d_out, int out_size) {
    (void)in_sizes; (void)n_in; (void)out_size;
    const float* x        = (const float*)d_in[0];
    const float* agent_w  = (const float*)d_in[1];
    const float* agent_b  = (const float*)d_in[2];
    const float* sos      = (const float*)d_in[3];
    const float* embedding= (const float*)d_in[4];
    const float* w_ih     = (const float*)d_in[5];
    const float* w_hh     = (const float*)d_in[6];
    const float* b_ih     = (const float*)d_in[7];
    const float* b_hh     = (const float*)d_in[8];
    const float* out_w    = (const float*)d_in[9];
    const float* out_b    = (const float*)d_in[10];

    float *c, *h0, *logits, *EP, *Wihp, *biasg;
    int* sym;
    __nv_bfloat16 *h6, *W6g, *W6o;
    cudaGetSymbolAddress((void**)&c, g_c);
    cudaGetSymbolAddress((void**)&h0, g_h0);
    cudaGetSymbolAddress((void**)&logits, g_logits);
    cudaGetSymbolAddress((void**)&EP, g_EP);
    cudaGetSymbolAddress((void**)&Wihp, g_Wihp);
    cudaGetSymbolAddress((void**)&biasg, g_biasg);
    cudaGetSymbolAddress((void**)&sym, g_sym);
    cudaGetSymbolAddress((void**)&h6, g_h6);
    cudaGetSymbolAddress((void**)&W6g, g_W6g);
    cudaGetSymbolAddress((void**)&W6o, g_W6o);
    __nv_bfloat16* h6a = h6;
    __nv_bfloat16* h6b = h6 + (size_t)B_ * K6;

    // Subkey chain for jax.random.key(1) (partitionable threefry).
    uint32_t skA[L_], skB[L_];
    uint32_t k0 = 0u, k1 = 1u;
    for (int t = 0; t < L_; t++) {
        uint32_t a0, a1, b0, b1;
        tf2x32(k0, k1, 0u, 0u, &a0, &a1);
        tf2x32(k0, k1, 0u, 1u, &b0, &b1);
        skA[t] = b0; skB[t] = b1;
        k0 = a0; k1 = a1;
    }

    float* out = (float*)d_out;
    float* o_seq   = out;
    float* o_probs = out + (size_t)B_ * LP1;
    float* o_logp  = o_probs + (size_t)B_ * LP1 * V_;
    float* o_ent   = o_logp + (size_t)B_ * LP1;

    init_kernel<<<(B_ * V_ + 255) / 256, 256>>>(o_seq, o_probs, o_logp, o_ent);
    permute_kernel<<<(H_ * G4 + 255) / 256, 256>>>(w_ih, b_ih, b_hh);
    sosrow_kernel<<<G4 / 256, 256>>>(sos);
    build_w6<<<(H_ * G4 + 255) / 256, 256>>>(w_hh, W6g, 1);
    build_w6<<<(H_ * G4 + 255) / 256, 256>>>(out_w, W6o, 0);

    // EP = embedding @ Wihp + biasg   [2048, 2048]
    gemm_f32<<<dim3(G4 / 128, V_ / 64), 256>>>(embedding, Wihp, E_, G4, biasg, EP);
    // h0 = x @ agent_w + agent_b
    gemm_f32<<<dim3(H_ / 128, B_ / 64), 256>>>(x, agent_w, IND, H_, agent_b, h0);
    split_h0_kernel<<<(B_ * H_ + 255) / 256, 256>>>();

    const dim3 mm_grid(V_ / BN, B_ / BM);   // (16, 8)
    for (int t = 0; t < L_; t++) {
        __nv_bfloat16* h_in  = (t & 1) ? h6b : h6a;
        __nv_bfloat16* h_out = (t & 1) ? h6a : h6b;
        // gates = h_in x W6g (+EP[sym]) -> LSTM -> c, h_out(split)
        mma_gemm<<<mm_grid, 256>>>(h_in, W6g, EP, sym, c, h_out,
                                   nullptr, nullptr, 1);
        // logits = h_out x W6o + out_b
        mma_gemm<<<mm_grid, 256>>>(h_out, W6o, nullptr, nullptr, nullptr,
                                   nullptr, out_b, logits, 0);
        sample_kernel<<<B_, 256>>>(o_seq, o_probs, o_logp, o_ent, skA[t], skB[t], t);
    }
}

// round 8
// speedup vs baseline: 3.4856x; 1.2666x over previous
#include <cuda_runtime.h>
#include <cuda_fp16.h>
#include <cstdint>
#include <cstddef>

static constexpr int B_   = 512;
static constexpr int H_   = 512;
static constexpr int E_   = 512;
static constexpr int V_   = 2048;
static constexpr int L_   = 32;
static constexpr int LP1  = 33;
static constexpr int IND  = 1024;
static constexpr int G4   = 4 * H_;   // 2048
static constexpr int K3   = 3 * H_;   // 1536 (fp16x2, 3-product folded K)
static constexpr int NCTA = 128;

// ---------------- persistent scratch (device globals; no allocation) ---------
__device__ float g_c[B_ * H_];
__device__ float g_h0[B_ * H_];
__device__ float g_logits[B_ * V_];
__device__ float g_EP[(V_ + 1) * G4];      // [2049,2048]; row V_ = sos
__device__ float g_Wihp[E_ * G4];
__device__ float g_biasg[G4];
__device__ int   g_sym[B_];
__device__ __half g_h3[2][B_ * K3];
__device__ __half g_W3g[G4 * K3];          // split+interleaved w_hh^T
__device__ __half g_W3o[V_ * K3];          // split out_w^T
__device__ uint32_t g_keys[2 * L_];
__device__ unsigned g_barcnt;

// ---------------- threefry2x32 (20 rounds) -----------------------------------
__host__ __device__ __forceinline__ uint32_t rotl32(uint32_t x, int d) {
    return (x << d) | (x >> (32 - d));
}
__host__ __device__ inline void tf2x32(uint32_t k0, uint32_t k1,
                                       uint32_t x0, uint32_t x1,
                                       uint32_t* o0, uint32_t* o1) {
    const uint32_t ks0 = k0, ks1 = k1, ks2 = k0 ^ k1 ^ 0x1BD11BDAu;
    x0 += ks0; x1 += ks1;
    x0 += x1; x1 = rotl32(x1, 13); x1 ^= x0;
    x0 += x1; x1 = rotl32(x1, 15); x1 ^= x0;
    x0 += x1; x1 = rotl32(x1, 26); x1 ^= x0;
    x0 += x1; x1 = rotl32(x1, 6);  x1 ^= x0;
    x0 += ks1; x1 += ks2 + 1u;
    x0 += x1; x1 = rotl32(x1, 17); x1 ^= x0;
    x0 += x1; x1 = rotl32(x1, 29); x1 ^= x0;
    x0 += x1; x1 = rotl32(x1, 16); x1 ^= x0;
    x0 += x1; x1 = rotl32(x1, 24); x1 ^= x0;
    x0 += ks2; x1 += ks0 + 2u;
    x0 += x1; x1 = rotl32(x1, 13); x1 ^= x0;
    x0 += x1; x1 = rotl32(x1, 15); x1 ^= x0;
    x0 += x1; x1 = rotl32(x1, 26); x1 ^= x0;
    x0 += x1; x1 = rotl32(x1, 6);  x1 ^= x0;
    x0 += ks0; x1 += ks1 + 3u;
    x0 += x1; x1 = rotl32(x1, 17); x1 ^= x0;
    x0 += x1; x1 = rotl32(x1, 29); x1 ^= x0;
    x0 += x1; x1 = rotl32(x1, 16); x1 ^= x0;
    x0 += x1; x1 = rotl32(x1, 24); x1 ^= x0;
    x0 += ks1; x1 += ks2 + 4u;
    x0 += x1; x1 = rotl32(x1, 13); x1 ^= x0;
    x0 += x1; x1 = rotl32(x1, 15); x1 ^= x0;
    x0 += x1; x1 = rotl32(x1, 26); x1 ^= x0;
    x0 += x1; x1 = rotl32(x1, 6);  x1 ^= x0;
    x0 += ks2; x1 += ks0 + 5u;
    *o0 = x0; *o1 = x1;
}

// ---------------- PTX wrappers -----------------------------------------------
__device__ __forceinline__ uint32_t smem_u32(const void* p) {
    uint32_t a;
    asm("{ .reg .u64 t; cvta.to.shared.u64 t, %1; cvt.u32.u64 %0, t; }"
        : "=r"(a) : "l"(p));
    return a;
}
__device__ __forceinline__ void cpasync16(uint32_t saddr, const void* g) {
    asm volatile("cp.async.cg.shared.global [%0], [%1], 16;" :: "r"(saddr), "l"(g));
}
__device__ __forceinline__ void cp_commit() {
    asm volatile("cp.async.commit_group;" ::: "memory");
}
template <int N>
__device__ __forceinline__ void cp_wait() {
    asm volatile("cp.async.wait_group %0;" :: "n"(N) : "memory");
}
__device__ __forceinline__ void ldsm4(uint32_t* r, uint32_t addr) {
    asm volatile("ldmatrix.sync.aligned.m8n8.x4.shared.b16 {%0,%1,%2,%3}, [%4];"
        : "=r"(r[0]), "=r"(r[1]), "=r"(r[2]), "=r"(r[3]) : "r"(addr));
}
__device__ __forceinline__ void mma16816(float* d, const uint32_t* a, const uint32_t* b) {
    asm volatile(
        "mma.sync.aligned.m16n8k16.row.col.f32.f16.f16.f32 "
        "{%0,%1,%2,%3}, {%4,%5,%6,%7}, {%8,%9}, {%0,%1,%2,%3};"
        : "+f"(d[0]), "+f"(d[1]), "+f"(d[2]), "+f"(d[3])
        : "r"(a[0]), "r"(a[1]), "r"(a[2]), "r"(a[3]), "r"(b[0]), "r"(b[1]));
}

// ---------------- fp16 rn-split ----------------------------------------------
__device__ __forceinline__ void split2h(float a, __half& a0, __half& a1) {
    a0 = __float2half_rn(a);
    a1 = __float2half_rn(a - __half2float(a0));
}

// ---------------- grid barrier -----------------------------------------------
__device__ __forceinline__ void grid_bar(unsigned target) {
    __threadfence();
    __syncthreads();
    if (threadIdx.x == 0) {
        atomicAdd(&g_barcnt, 1u);
        while (atomicAdd(&g_barcnt, 0u) < target) __nanosleep(64);
    }
    __syncthreads();
    __threadfence();
}

// ============================================================================
// persistent kernel: 32 x (gates GEMM+LSTM | logits GEMM | sample)
// ============================================================================
static constexpr int BM = 64, BN = 128, BK = 64;
static constexpr int NCH = K3 / BK;       // 24
static constexpr int ASTG = BM * BK * 2;  // 8192
static constexpr int BSTG = BN * BK * 2;  // 16384

struct SmemU {
    union {
        struct { uint8_t A[2][ASTG]; uint8_t B[2][BSTG]; } t;   // 49152
        float epi[64][132];
        struct { float red[256]; int idx[256]; } s;
    };
};

__device__ __forceinline__ void gemm_phase(
    SmemU* sm, const __half* __restrict__ A, const __half* __restrict__ W,
    const float* __restrict__ EP, const int* __restrict__ sym,
    float* __restrict__ c_state, __half* __restrict__ h3out,
    const float* __restrict__ bias, float* __restrict__ out, int mode)
{
    const int tid = threadIdx.x;
    const int wid = tid >> 5, lane = tid & 31;
    const int wm = wid & 1, wn = wid >> 1;
    const int ci = blockIdx.x;
    const int bn = (ci & 15) * BN, bm = (ci >> 4) * BM;

    const uint32_t sA = smem_u32(&sm->t.A[0][0]);
    const uint32_t sB = smem_u32(&sm->t.B[0][0]);

    const int rA = wm * 32 + (lane & 7) + ((lane >> 3) & 1) * 8;
    const int cbA = lane >> 4;
    const int rB = wn * 32 + ((lane >> 4) << 3) + (lane & 7);
    const int cbB = (lane >> 3) & 1;

    int aRow[2], aCol[2]; uint32_t aS[2];
    #pragma unroll
    for (int i = 0; i < 2; i++) {
        const int s = tid + i * 256;
        aRow[i] = s >> 3; aCol[i] = s & 7;
        aS[i] = (uint32_t)(aRow[i] * 128 + ((aCol[i] ^ (aRow[i] & 7)) << 4));
    }
    int bRow[4], bCol[4]; uint32_t bS[4];
    #pragma unroll
    for (int i = 0; i < 4; i++) {
        const int s = tid + i * 256;
        bRow[i] = s >> 3; bCol[i] = s & 7;
        bS[i] = (uint32_t)(bRow[i] * 128 + ((bCol[i] ^ (bRow[i] & 7)) << 4));
    }

    float acc[2][4][4] = {};

    #pragma unroll
    for (int i = 0; i < 2; i++)
        cpasync16(sA + aS[i], A + (size_t)(bm + aRow[i]) * K3 + aCol[i] * 8);
    #pragma unroll
    for (int i = 0; i < 4; i++)
        cpasync16(sB + bS[i], W + (size_t)(bn + bRow[i]) * K3 + bCol[i] * 8);
    cp_commit();

    for (int ck = 0; ck < NCH; ck++) {
        const int buf = ck & 1;
        if (ck + 1 < NCH) {
            const int nb = (ck + 1) & 1;
            const size_t koff = (size_t)(ck + 1) * BK;
            #pragma unroll
            for (int i = 0; i < 2; i++)
                cpasync16(sA + nb * ASTG + aS[i],
                          A + (size_t)(bm + aRow[i]) * K3 + koff + aCol[i] * 8);
            #pragma unroll
            for (int i = 0; i < 4; i++)
                cpasync16(sB + nb * BSTG + bS[i],
                          W + (size_t)(bn + bRow[i]) * K3 + koff + bCol[i] * 8);
            cp_commit();
            cp_wait<1>();
        } else {
            cp_wait<0>();
        }
        __syncthreads();

        const uint32_t Ab = sA + buf * ASTG;
        const uint32_t Bb = sB + buf * BSTG;
        #pragma unroll
        for (int s = 0; s < 4; s++) {
            uint32_t afr[2][4];
            #pragma unroll
            for (int mi = 0; mi < 2; mi++) {
                const int row = rA + mi * 16;
                ldsm4(afr[mi], Ab + row * 128 + (((2 * s + cbA) ^ (row & 7)) << 4));
            }
            uint32_t bfr[4][2];
            #pragma unroll
            for (int half = 0; half < 2; half++) {
                uint32_t q[4];
                const int row = rB + half * 16;
                ldsm4(q, Bb + row * 128 + (((2 * s + cbB) ^ (row & 7)) << 4));
                bfr[2 * half][0] = q[0]; bfr[2 * half][1] = q[1];
                bfr[2 * half + 1][0] = q[2]; bfr[2 * half + 1][1] = q[3];
            }
            #pragma unroll
            for (int mi = 0; mi < 2; mi++)
                #pragma unroll
                for (int ni = 0; ni < 4; ni++)
                    mma16816(acc[mi][ni], afr[mi], bfr[ni]);
        }
        __syncthreads();
    }

    if (mode == 0) {
        #pragma unroll
        for (int mi = 0; mi < 2; mi++) {
            const int R0 = bm + wm * 32 + mi * 16 + (lane >> 2);
            #pragma unroll
            for (int ni = 0; ni < 4; ni++) {
                const int C0 = bn + wn * 32 + ni * 8 + 2 * (lane & 3);
                const float b0 = bias[C0], b1 = bias[C0 + 1];
                float2 v0 = make_float2(acc[mi][ni][0] + b0, acc[mi][ni][1] + b1);
                float2 v1 = make_float2(acc[mi][ni][2] + b0, acc[mi][ni][3] + b1);
                *(float2*)(out + (size_t)R0 * V_ + C0) = v0;
                *(float2*)(out + (size_t)(R0 + 8) * V_ + C0) = v1;
            }
        }
    } else {
        #pragma unroll
        for (int mi = 0; mi < 2; mi++) {
            const int r0 = wm * 32 + mi * 16 + (lane >> 2);
            #pragma unroll
            for (int ni = 0; ni < 4; ni++) {
                const int c0 = wn * 32 + ni * 8 + 2 * (lane & 3);
                sm->epi[r0][c0]     = acc[mi][ni][0];
                sm->epi[r0][c0 + 1] = acc[mi][ni][1];
                sm->epi[r0 + 8][c0]     = acc[mi][ni][2];
                sm->epi[r0 + 8][c0 + 1] = acc[mi][ni][3];
            }
        }
        __syncthreads();
        const int r = tid >> 2;
        const int nl0 = (tid & 3) * 8;
        const int R = bm + r;
        const int s = __ldg(sym + R);
        const float* eprow = EP + (size_t)s * G4;
        #pragma unroll
        for (int j = 0; j < 8; j++) {
            const int nl = nl0 + j;
            const int col4 = bn + 4 * nl;
            const float4 ep = *(const float4*)(eprow + col4);
            const float gi = sm->epi[r][4 * nl + 0] + ep.x;
            const float gf = sm->epi[r][4 * nl + 1] + ep.y;
            const float gg = sm->epi[r][4 * nl + 2] + ep.z;
            const float go = sm->epi[r][4 * nl + 3] + ep.w;
            const float si = 1.0f / (1.0f + expf(-gi));
            const float sf = 1.0f / (1.0f + expf(-gf));
            const float so = 1.0f / (1.0f + expf(-go));
            const int ng = (bn >> 2) + nl;
            const size_t idx = (size_t)R * H_ + ng;
            const float cn = sf * c_state[idx] + si * tanhf(gg);
            c_state[idx] = cn;
            const float h = so * tanhf(cn);
            __half a0, a1;
            split2h(h, a0, a1);
            __half* o = h3out + (size_t)R * K3 + 3 * ng;
            o[0] = a0; o[1] = a0; o[2] = a1;     // j0:a0 j1:a0 j2:a1
        }
        __syncthreads();
    }
}

__device__ __forceinline__ void sample_phase(
    SmemU* sm, int t, int* __restrict__ sym,
    const float* __restrict__ logits,
    float* __restrict__ o_seq, float* __restrict__ o_probs,
    float* __restrict__ o_logp, float* __restrict__ o_ent)
{
    const int tid = threadIdx.x;
    const uint32_t sk0 = g_keys[2 * t], sk1 = g_keys[2 * t + 1];
    for (int j = 0; j < 4; j++) {
        const int b = blockIdx.x * 4 + j;
        const float* row = logits + (size_t)b * V_;

        float xs[8];
        float mx = -3.402823466e38f;
        #pragma unroll
        for (int i = 0; i < 8; i++) {
            xs[i] = row[tid + i * 256];
            mx = fmaxf(mx, xs[i]);
        }
        sm->s.red[tid] = mx; __syncthreads();
        for (int s = 128; s > 0; s >>= 1) {
            if (tid < s) sm->s.red[tid] = fmaxf(sm->s.red[tid], sm->s.red[tid + s]);
            __syncthreads();
        }
        mx = sm->s.red[0]; __syncthreads();

        float se = 0.0f;
        #pragma unroll
        for (int i = 0; i < 8; i++) { xs[i] -= mx; se += expf(xs[i]); }
        sm->s.red[tid] = se; __syncthreads();
        for (int s = 128; s > 0; s >>= 1) {
            if (tid < s) sm->s.red[tid] += sm->s.red[tid + s];
            __syncthreads();
        }
        se = sm->s.red[0]; __syncthreads();
        const float lse = logf(se);

        float* probs_row = o_probs + ((size_t)b * LP1 + t) * V_;
        float ent = 0.0f;
        float bestv = -3.402823466e38f;
        int   besti = V_;
        #pragma unroll
        for (int i = 0; i < 8; i++) {
            const int v = tid + i * 256;
            const float lsm = xs[i] - lse;
            const float p = expf(lsm);
            probs_row[v] = p;
            ent += p * lsm;
            uint32_t o0, o1;
            tf2x32(sk0, sk1, 0u, (uint32_t)(b * V_ + v), &o0, &o1);
            const uint32_t bits = o0 ^ o1;
            const float f = __uint_as_float((bits >> 9) | 0x3f800000u) - 1.0f;
            const float u = (f == 0.0f) ? 1.1754943508222875e-38f : f;
            const float g = -logf(-logf(u));
            const float val = lsm + g;
            if (val > bestv) { bestv = val; besti = v; }
        }

        sm->s.red[tid] = ent; __syncthreads();
        for (int s = 128; s > 0; s >>= 1) {
            if (tid < s) sm->s.red[tid] += sm->s.red[tid + s];
            __syncthreads();
        }
        const float entTot = sm->s.red[0]; __syncthreads();

        sm->s.red[tid] = bestv; sm->s.idx[tid] = besti; __syncthreads();
        for (int s = 128; s > 0; s >>= 1) {
            if (tid < s) {
                const float v2 = sm->s.red[tid + s];
                const int   i2 = sm->s.idx[tid + s];
                if (v2 > sm->s.red[tid] ||
                    (v2 == sm->s.red[tid] && i2 < sm->s.idx[tid])) {
                    sm->s.red[tid] = v2; sm->s.idx[tid] = i2;
                }
            }
            __syncthreads();
        }
        if (tid == 0) {
            const int sv = sm->s.idx[0];
            sym[b] = sv;
            o_ent[(size_t)b * LP1 + t]  = -entTot;
            o_seq[(size_t)b * LP1 + t]  = (float)sv;
            o_logp[(size_t)b * LP1 + t] = (row[sv] - mx) - lse;
        }
        __syncthreads();
    }
}

__global__ __launch_bounds__(256, 1) void persist_kernel(
    const float* __restrict__ EP, int* __restrict__ sym,
    float* __restrict__ c_state,
    __half* __restrict__ h3a, __half* __restrict__ h3b,
    const __half* __restrict__ W3g, const __half* __restrict__ W3o,
    const float* __restrict__ out_b, float* __restrict__ logits,
    float* __restrict__ o_seq, float* __restrict__ o_probs,
    float* __restrict__ o_logp, float* __restrict__ o_ent)
{
    __shared__ SmemU sm;
    unsigned bt = 0;
    for (int t = 0; t < L_; t++) {
        __half* hin  = (t & 1) ? h3b : h3a;
        __half* hout = (t & 1) ? h3a : h3b;
        gemm_phase(&sm, hin, W3g, EP, sym, c_state, hout, nullptr, nullptr, 1);
        bt += NCTA; grid_bar(bt);
        gemm_phase(&sm, hout, W3o, nullptr, nullptr, nullptr, nullptr,
                   out_b, logits, 0);
        bt += NCTA; grid_bar(bt);
        sample_phase(&sm, t, sym, logits, o_seq, o_probs, o_logp, o_ent);
        bt += NCTA; grid_bar(bt);
    }
}

// ---------------- SIMT fp32 GEMM (prep only: EP, h0) -------------------------
__global__ __launch_bounds__(256) void gemm_f32(
    const float* __restrict__ A, const float* __restrict__ W,
    int K, int N, const float* __restrict__ bias, float* __restrict__ C)
{
    __shared__ __align__(16) float As[16][68];
    __shared__ __align__(16) float Bs[16][128];
    const int tid = threadIdx.x;
    const int bn = blockIdx.x * 128, bm = blockIdx.y * 64;
    const int tx = tid & 31, ty = tid >> 5;
    const int r0 = ty * 8, c0 = tx * 4;
    const int arow = tid >> 2, acol = (tid & 3) << 2;
    const int wrow = tid >> 5, wcol = (tid & 31) << 2;

    const float* Aptr  = A + (size_t)(bm + arow) * K + acol;
    const float* Wptr0 = W + (size_t)wrow * N + bn + wcol;
    const float* Wptr1 = Wptr0 + (size_t)8 * N;
    float4 pa  = *(const float4*)(Aptr);
    float4 pb0 = *(const float4*)(Wptr0);
    float4 pb1 = *(const float4*)(Wptr1);
    float acc[8][4] = {};
    for (int k0 = 0; k0 < K; k0 += 16) {
        As[acol + 0][arow] = pa.x; As[acol + 1][arow] = pa.y;
        As[acol + 2][arow] = pa.z; As[acol + 3][arow] = pa.w;
        *(float4*)(&Bs[wrow][wcol])     = pb0;
        *(float4*)(&Bs[wrow + 8][wcol]) = pb1;
        __syncthreads();
        if (k0 + 16 < K) {
            pa  = *(const float4*)(Aptr + k0 + 16);
            pb0 = *(const float4*)(Wptr0 + (size_t)(k0 + 16) * N);
            pb1 = *(const float4*)(Wptr1 + (size_t)(k0 + 16) * N);
        }
        #pragma unroll
        for (int k = 0; k < 16; k++) {
            float4 a0 = *(const float4*)(&As[k][r0]);
            float4 a1 = *(const float4*)(&As[k][r0 + 4]);
            float4 b  = *(const float4*)(&Bs[k][c0]);
            float av[8] = {a0.x, a0.y, a0.z, a0.w, a1.x, a1.y, a1.z, a1.w};
            #pragma unroll
            for (int i = 0; i < 8; i++) {
                acc[i][0] += av[i] * b.x; acc[i][1] += av[i] * b.y;
                acc[i][2] += av[i] * b.z; acc[i][3] += av[i] * b.w;
            }
        }
        __syncthreads();
    }
    float4 bv = make_float4(0.f, 0.f, 0.f, 0.f);
    if (bias) bv = *(const float4*)(bias + bn + c0);
    #pragma unroll
    for (int i = 0; i < 8; i++) {
        const int rr = bm + r0 + i;
        float4 v;
        v.x = acc[i][0] + bv.x; v.y = acc[i][1] + bv.y;
        v.z = acc[i][2] + bv.z; v.w = acc[i][3] + bv.w;
        *(float4*)(C + (size_t)rr * N + bn + c0) = v;
    }
}

// ---------------- weight / state prep ----------------------------------------
__global__ __launch_bounds__(256) void permute_kernel(
    const float* __restrict__ w_ih, const float* __restrict__ b_ih,
    const float* __restrict__ b_hh)
{
    const int idx = blockIdx.x * 256 + threadIdx.x;
    const int k = idx >> 11, col = idx & (G4 - 1);
    const int n = col >> 2, g = col & 3;
    const int src = g * H_ + n;
    g_Wihp[idx] = w_ih[(size_t)k * G4 + src];
    if (idx < G4) g_biasg[idx] = b_ih[src] + b_hh[src];
}

__global__ __launch_bounds__(256) void build_w3(
    const float* __restrict__ W, __half* __restrict__ out, int interleave)
{
    const int idx = blockIdx.x * 256 + threadIdx.x;   // < 2048*512
    const int k = idx >> 11, ncol = idx & (G4 - 1);
    const int src = interleave ? ((ncol & 3) * H_ + (ncol >> 2)) : ncol;
    const float w = W[(size_t)k * 2048 + src];
    __half b0, b1;
    b0 = __float2half_rn(w);
    b1 = __float2half_rn(w - __half2float(b0));
    __half* o = out + (size_t)ncol * K3 + 3 * k;
    o[0] = b0; o[1] = b1; o[2] = b0;       // j0:b0 j1:b1 j2:b0
}

__global__ __launch_bounds__(256) void split_h0_kernel() {
    const int idx = blockIdx.x * 256 + threadIdx.x;   // < 512*512
    const int r = idx >> 9, n = idx & (H_ - 1);
    __half a0, a1;
    a0 = __float2half_rn(g_h0[idx]);
    a1 = __float2half_rn(g_h0[idx] - __half2float(a0));
    __half* o = g_h3[0] + (size_t)r * K3 + 3 * n;
    o[0] = a0; o[1] = a0; o[2] = a1;       // j0:a0 j1:a0 j2:a1
}

__global__ __launch_bounds__(256) void sosrow_kernel(const float* __restrict__ sos) {
    const int c = blockIdx.x * 256 + threadIdx.x;
    float acc = g_biasg[c];
    for (int k = 0; k < E_; k++)
        acc += sos[k] * g_Wihp[(size_t)k * G4 + c];
    g_EP[(size_t)V_ * G4 + c] = acc;
}

__global__ __launch_bounds__(256) void init_kernel(
    float* __restrict__ o_seq, float* __restrict__ o_probs,
    float* __restrict__ o_logp, float* __restrict__ o_ent)
{
    const int i = blockIdx.x * 256 + threadIdx.x;
    if (i == 0) {
        g_barcnt = 0;
        uint32_t k0 = 0u, k1 = 1u;
        for (int t = 0; t < L_; t++) {
            uint32_t a0, a1, b0, b1;
            tf2x32(k0, k1, 0u, 0u, &a0, &a1);
            tf2x32(k0, k1, 0u, 1u, &b0, &b1);
            g_keys[2 * t] = b0; g_keys[2 * t + 1] = b1;
            k0 = a0; k1 = a1;
        }
    }
    if (i < B_ * H_) g_c[i] = 0.0f;
    if (i < B_) {
        g_sym[i] = V_;
        o_seq[(size_t)i * LP1 + L_]  = 0.0f;
        o_logp[(size_t)i * LP1 + L_] = 0.0f;
        o_ent[(size_t)i * LP1 + L_]  = 0.0f;
    }
    if (i < B_ * V_) {
        const int b = i >> 11, v = i & (V_ - 1);
        o_probs[((size_t)b * LP1 + L_) * V_ + v] = 1.0f;
    }
}

// ---------------- host launcher ----------------------------------------------
extern "C" void kernel_launch(void* const* d_in, const int* in_sizes, int n_in,
                              void* d_out, int out_size) {
    (void)in_sizes; (void)n_in; (void)out_size;
    const float* x        = (const float*)d_in[0];
    const float* agent_w  = (const float*)d_in[1];
    const float* agent_b  = (const float*)d_in[2];
    const float* sos      = (const float*)d_in[3];
    const float* w_ih     = (const float*)d_in[5];
    const float* w_hh     = (const float*)d_in[6];
    const float* b_ih     = (const float*)d_in[7];
    const float* b_hh     = (const float*)d_in[8];
    const float* out_w    = (const float*)d_in[9];
    const float* out_b    = (const float*)d_in[10];
    const float* embedding= (const float*)d_in[4];

    float *c, *h0, *logits, *EP, *Wihp, *biasg;
    int* sym;
    __half *h3, *W3g, *W3o;
    cudaGetSymbolAddress((void**)&c, g_c);
    cudaGetSymbolAddress((void**)&h0, g_h0);
    cudaGetSymbolAddress((void**)&logits, g_logits);
    cudaGetSymbolAddress((void**)&EP, g_EP);
    cudaGetSymbolAddress((void**)&Wihp, g_Wihp);
    cudaGetSymbolAddress((void**)&biasg, g_biasg);
    cudaGetSymbolAddress((void**)&sym, g_sym);
    cudaGetSymbolAddress((void**)&h3, g_h3);
    cudaGetSymbolAddress((void**)&W3g, g_W3g);
    cudaGetSymbolAddress((void**)&W3o, g_W3o);
    __half* h3a = h3;
    __half* h3b = h3 + (size_t)B_ * K3;

    float* out = (float*)d_out;
    float* o_seq   = out;
    float* o_probs = out + (size_t)B_ * LP1;
    float* o_logp  = o_probs + (size_t)B_ * LP1 * V_;
    float* o_ent   = o_logp + (size_t)B_ * LP1;

    init_kernel<<<(B_ * V_ + 255) / 256, 256>>>(o_seq, o_probs, o_logp, o_ent);
    permute_kernel<<<(H_ * G4 + 255) / 256, 256>>>(w_ih, b_ih, b_hh);
    sosrow_kernel<<<G4 / 256, 256>>>(sos);
    build_w3<<<(H_ * G4 + 255) / 256, 256>>>(w_hh, W3g, 1);
    build_w3<<<(H_ * G4 + 255) / 256, 256>>>(out_w, W3o, 0);

    // EP = embedding @ Wihp + biasg   [2048, 2048]
    gemm_f32<<<dim3(G4 / 128, V_ / 64), 256>>>(embedding, Wihp, E_, G4, biasg, EP);
    // h0 = x @ agent_w + agent_b
    gemm_f32<<<dim3(H_ / 128, B_ / 64), 256>>>(x, agent_w, IND, H_, agent_b, h0);
    split_h0_kernel<<<(B_ * H_ + 255) / 256, 256>>>();

    persist_kernel<<<NCTA, 256>>>(EP, sym, c, h3a, h3b, W3g, W3o,
                                  out_b, logits,
                                  o_seq, o_probs, o_logp, o_ent);
}